// round 2
// baseline (speedup 1.0000x reference)
#include <cuda_runtime.h>
#include <math.h>

#define NSc 16
#define NVc 8
#define HEc 32
#define Dc  40
#define WNc 640
#define NNODES 10000
#define NEDGES 160000
#define C110f 0.57735026918962576f
#define C111f 0.70710678118654752f
#define EPSf 1e-5f

// ---------------- device scratch ----------------
__device__ float g_q[NNODES * Dc];
__device__ float g_attn[NEDGES];
__device__ float g_expv[NEDGES];
__device__ float g_vout[NEDGES * Dc];
__device__ float g_m[NNODES];
__device__ float g_denom[NNODES];
__device__ float g_upd[NNODES * Dc];
__device__ float g_bn[40];

// ---------------- helpers ----------------
__device__ __forceinline__ void atomicMaxF(float* addr, float v) {
    if (v >= 0.0f) atomicMax((int*)addr, __float_as_int(v));
    else           atomicMin((unsigned int*)addr, __float_as_uint(v));
}
__device__ __forceinline__ float4 f4zero() { return make_float4(0.f, 0.f, 0.f, 0.f); }
__device__ __forceinline__ float4 f4fma(float4 a, float4 b, float4 c) {
    return make_float4(fmaf(a.x, b.x, c.x), fmaf(a.y, b.y, c.y),
                       fmaf(a.z, b.z, c.z), fmaf(a.w, b.w, c.w));
}
__device__ __forceinline__ float4 f4mul(float4 a, float4 b) {
    return make_float4(a.x * b.x, a.y * b.y, a.z * b.z, a.w * b.w);
}
__device__ __forceinline__ float4 f4add(float4 a, float4 b) {
    return make_float4(a.x + b.x, a.y + b.y, a.z + b.z, a.w + b.w);
}
__device__ __forceinline__ float4 shflxor4(float4 v, int m) {
    v.x = __shfl_xor_sync(0xffffffffu, v.x, m);
    v.y = __shfl_xor_sync(0xffffffffu, v.y, m);
    v.z = __shfl_xor_sync(0xffffffffu, v.z, m);
    v.w = __shfl_xor_sync(0xffffffffu, v.w, m);
    return v;
}
__device__ __forceinline__ float4 ld4(const float* p) { return *(const float4*)p; }

// ---------------- init ----------------
__global__ void k_init() {
    int t = blockIdx.x * blockDim.x + threadIdx.x;
    if (t < NNODES) {
        g_m[t] = __int_as_float(0xff800000);
        g_denom[t] = 0.f;
    }
    if (t < NNODES * Dc) g_upd[t] = 0.f;
    if (t < 40) g_bn[t] = 0.f;
}

// ---------------- per-node query projection ----------------
__global__ void k_q(const float* __restrict__ atom,
                    const float* __restrict__ Wqs,
                    const float* __restrict__ Wqv) {
    __shared__ float sWs[NSc * NSc];
    __shared__ float sWv[NVc * NVc];
    int tid = threadIdx.x;
    for (int i = tid; i < NSc * NSc; i += blockDim.x) sWs[i] = Wqs[i];
    for (int i = tid; i < NVc * NVc; i += blockDim.x) sWv[i] = Wqv[i];
    __syncthreads();
    int n = blockIdx.x * blockDim.x + tid;
    if (n >= NNODES) return;
    float s[NSc], v[NVc * 3];
    #pragma unroll
    for (int i = 0; i < NSc; i++) s[i] = atom[n * Dc + i];
    #pragma unroll
    for (int i = 0; i < NVc * 3; i++) v[i] = atom[n * Dc + NSc + i];
    #pragma unroll
    for (int o = 0; o < NSc; o++) {
        float acc = 0.f;
        #pragma unroll
        for (int i = 0; i < NSc; i++) acc = fmaf(s[i], sWs[i * NSc + o], acc);
        g_q[n * Dc + o] = acc;
    }
    #pragma unroll
    for (int o = 0; o < NVc; o++) {
        #pragma unroll
        for (int d = 0; d < 3; d++) {
            float acc = 0.f;
            #pragma unroll
            for (int i = 0; i < NVc; i++) acc = fmaf(v[i * 3 + d], sWv[i * NVc + o], acc);
            g_q[n * Dc + NSc + o * 3 + d] = acc;
        }
    }
}

// ---------------- fused edge kernel ----------------
struct __align__(16) WS {
    float sefT[HEc][4];
    float h[2][HEc][4];
    float sq[Dc][4];
    float sx[4][Dc];
    float xs_[NSc][4];
    float as_[NSc][4];
    float dotc_[NVc][4];
    float xvs_[NVc * 3][4];
    float crossc_[NVc * 3][4];
    float shv_[3][4];
    float shs_[4];
    int ssrc[4];
};
static_assert(sizeof(WS) == 4304, "WS size");

#define SMEM_WEIGHT_FLOATS (2*32*640 + 2*640 + 2*32*32 + 2*32)
#define SMEM_EDGE_BYTES (SMEM_WEIGHT_FLOATS * 4 + 8 * (int)sizeof(WS))

__global__ void __launch_bounds__(256, 1) k_edge(
    const float* __restrict__ atom, const float* __restrict__ efeat,
    const float* __restrict__ esh,
    const float* __restrict__ kw1, const float* __restrict__ kb1,
    const float* __restrict__ kw2, const float* __restrict__ kb2,
    const float* __restrict__ vw1, const float* __restrict__ vb1,
    const float* __restrict__ vw2, const float* __restrict__ vb2,
    const int* __restrict__ eidx)
{
    extern __shared__ float smem[];
    float* sW2 = smem;                 // [2][32][640]
    float* sB2 = sW2 + 2 * 32 * 640;   // [2][640]
    float* sW1 = sB2 + 2 * 640;        // [2][32][32]
    float* sB1 = sW1 + 2 * 32 * 32;    // [2][32]
    WS* wsbase = (WS*)(sB1 + 2 * 32);

    int tid = threadIdx.x;
    for (int i = tid; i < 32 * 640; i += 256) { sW2[i] = kw2[i]; sW2[20480 + i] = vw2[i]; }
    for (int i = tid; i < 640; i += 256)      { sB2[i] = kb2[i]; sB2[640 + i] = vb2[i]; }
    for (int i = tid; i < 1024; i += 256)     { sW1[i] = kw1[i]; sW1[1024 + i] = vw1[i]; }
    if (tid < 32) { sB1[tid] = kb1[tid]; sB1[32 + tid] = vb1[tid]; }
    __syncthreads();

    int wid = tid >> 5, lane = tid & 31;
    WS* ws = wsbase + wid;
    int gwarp = blockIdx.x * 8 + wid;
    int nwarps = gridDim.x * 8;
    int hi16 = lane >> 4;
    int hi8 = lane >> 3;

    for (int g = gwarp; g < NEDGES / 4; g += nwarps) {
        int e0 = g * 4;
        // gather
        #pragma unroll
        for (int e = 0; e < 4; e++) {
            int edge = e0 + e;
            int dst = eidx[edge];
            int src = eidx[NEDGES + edge];
            ws->sx[e][lane] = atom[dst * Dc + lane];
            ws->sq[lane][e] = g_q[src * Dc + lane];
            if (lane < 8) {
                ws->sx[e][32 + lane] = atom[dst * Dc + 32 + lane];
                ws->sq[32 + lane][e] = g_q[src * Dc + 32 + lane];
            }
            ws->sefT[lane][e] = efeat[edge * HEc + lane];
            if (lane == 0) ws->ssrc[e] = src;
            if (lane < 4) {
                float sv = esh[edge * 4 + lane];
                if (lane == 0) ws->shs_[e] = sv;
                else ws->shv_[lane - 1][e] = sv;
            }
        }
        __syncwarp();
        // derived per-edge coefficients
        #pragma unroll
        for (int e = 0; e < 4; e++) {
            float s0 = ws->shs_[e];
            if (lane < 16) {
                float x = ws->sx[e][lane];
                ws->xs_[lane][e] = x;
                ws->as_[lane][e] = x * s0;
            } else if (lane < 24) {
                int i = lane - 16;
                float ax = ws->sx[e][16 + 3 * i], ay = ws->sx[e][17 + 3 * i], az = ws->sx[e][18 + 3 * i];
                float bx = ws->shv_[0][e], by = ws->shv_[1][e], bz = ws->shv_[2][e];
                ws->dotc_[i][e] = C110f * (ax * bx + ay * by + az * bz);
                ws->crossc_[3 * i + 0][e] = C111f * (ay * bz - az * by);
                ws->crossc_[3 * i + 1][e] = C111f * (az * bx - ax * bz);
                ws->crossc_[3 * i + 2][e] = C111f * (ax * by - ay * bx);
                ws->xvs_[3 * i + 0][e] = ax * s0;
                ws->xvs_[3 * i + 1][e] = ay * s0;
                ws->xvs_[3 * i + 2][e] = az * s0;
            }
        }
        __syncwarp();
        // hidden layer, both MLPs (lane = hidden unit, vec over 4 edges)
        {
            float bk = sB1[lane], bv = sB1[32 + lane];
            float4 hk = make_float4(bk, bk, bk, bk);
            float4 hv = make_float4(bv, bv, bv, bv);
            const float4* efp = (const float4*)ws->sefT;
            #pragma unroll 8
            for (int j = 0; j < 32; j++) {
                float4 e4 = efp[j];
                float wk = sW1[j * 32 + lane];
                float wv2 = sW1[1024 + j * 32 + lane];
                hk = f4fma(make_float4(wk, wk, wk, wk), e4, hk);
                hv = f4fma(make_float4(wv2, wv2, wv2, wv2), e4, hv);
            }
            hk.x = fmaxf(hk.x, 0.f); hk.y = fmaxf(hk.y, 0.f); hk.z = fmaxf(hk.z, 0.f); hk.w = fmaxf(hk.w, 0.f);
            hv.x = fmaxf(hv.x, 0.f); hv.y = fmaxf(hv.y, 0.f); hv.z = fmaxf(hv.z, 0.f); hv.w = fmaxf(hv.w, 0.f);
            ((float4*)ws->h)[lane] = hk;
            ((float4*)ws->h)[32 + lane] = hv;
        }
        __syncwarp();

        // per matrix: 640-wide matvec (n = 32c+lane) + TP epilogue
        #pragma unroll
        for (int mat = 0; mat < 2; mat++) {
            float4 acc[20];
            const float* b2p = sB2 + mat * 640 + lane;
            #pragma unroll
            for (int c = 0; c < 20; c++) {
                float b = b2p[c * 32];
                acc[c] = make_float4(b, b, b, b);
            }
            const float* w2p = sW2 + mat * 20480 + lane;
            const float4* h4p = (const float4*)(ws->h) + mat * 32;
            #pragma unroll 4
            for (int j = 0; j < 32; j++) {
                float4 hj = h4p[j];
                const float* wr = w2p + j * 640;
                #pragma unroll
                for (int c = 0; c < 20; c++) {
                    float w = wr[c * 32];
                    acc[c].x = fmaf(w, hj.x, acc[c].x);
                    acc[c].y = fmaf(w, hj.y, acc[c].y);
                    acc[c].z = fmaf(w, hj.z, acc[c].z);
                    acc[c].w = fmaf(w, hj.w, acc[c].w);
                }
            }
            // scalar outputs: o = lane&15, i = 2c'+hi16
            float4 ps = f4zero();
            #pragma unroll
            for (int c = 0; c < 8; c++)  ps = f4fma(acc[c], ld4(ws->as_[2 * c + hi16]), ps);
            #pragma unroll
            for (int c = 8; c < 12; c++) ps = f4fma(acc[c], ld4(ws->dotc_[2 * (c - 8) + hi16]), ps);
            ps = f4add(ps, shflxor4(ps, 16));
            // vector outputs: o = lane&7, i = 4c'+hi8
            float4 p3 = f4zero();
            #pragma unroll
            for (int c = 12; c < 16; c++) p3 = f4fma(acc[c], ld4(ws->xs_[4 * (c - 12) + hi8]), p3);
            float4 pv0 = f4mul(p3, ld4(ws->shv_[0]));
            float4 pv1 = f4mul(p3, ld4(ws->shv_[1]));
            float4 pv2 = f4mul(p3, ld4(ws->shv_[2]));
            #pragma unroll
            for (int c = 16; c < 18; c++) {
                int i = 4 * (c - 16) + hi8;
                pv0 = f4fma(acc[c], ld4(ws->xvs_[3 * i + 0]), pv0);
                pv1 = f4fma(acc[c], ld4(ws->xvs_[3 * i + 1]), pv1);
                pv2 = f4fma(acc[c], ld4(ws->xvs_[3 * i + 2]), pv2);
            }
            #pragma unroll
            for (int c = 18; c < 20; c++) {
                int i = 4 * (c - 18) + hi8;
                pv0 = f4fma(acc[c], ld4(ws->crossc_[3 * i + 0]), pv0);
                pv1 = f4fma(acc[c], ld4(ws->crossc_[3 * i + 1]), pv1);
                pv2 = f4fma(acc[c], ld4(ws->crossc_[3 * i + 2]), pv2);
            }
            pv0 = f4add(pv0, shflxor4(pv0, 8)); pv0 = f4add(pv0, shflxor4(pv0, 16));
            pv1 = f4add(pv1, shflxor4(pv1, 8)); pv1 = f4add(pv1, shflxor4(pv1, 16));
            pv2 = f4add(pv2, shflxor4(pv2, 8)); pv2 = f4add(pv2, shflxor4(pv2, 16));

            if (mat == 0) {
                float4 t = f4zero();
                if (lane < 16) t = f4mul(ps, ld4(ws->sq[lane]));
                if (lane < 8) {
                    t = f4fma(pv0, ld4(ws->sq[16 + 3 * lane + 0]), t);
                    t = f4fma(pv1, ld4(ws->sq[16 + 3 * lane + 1]), t);
                    t = f4fma(pv2, ld4(ws->sq[16 + 3 * lane + 2]), t);
                }
                #pragma unroll
                for (int off = 16; off > 0; off >>= 1) t = f4add(t, shflxor4(t, off));
                if (lane == 0) {
                    g_attn[e0 + 0] = t.x; atomicMaxF(&g_m[ws->ssrc[0]], t.x);
                    g_attn[e0 + 1] = t.y; atomicMaxF(&g_m[ws->ssrc[1]], t.y);
                    g_attn[e0 + 2] = t.z; atomicMaxF(&g_m[ws->ssrc[2]], t.z);
                    g_attn[e0 + 3] = t.w; atomicMaxF(&g_m[ws->ssrc[3]], t.w);
                }
            } else {
                if (lane < 16) {
                    g_vout[(e0 + 0) * Dc + lane] = ps.x;
                    g_vout[(e0 + 1) * Dc + lane] = ps.y;
                    g_vout[(e0 + 2) * Dc + lane] = ps.z;
                    g_vout[(e0 + 3) * Dc + lane] = ps.w;
                }
                if (lane < 8) {
                    int b0 = 16 + 3 * lane;
                    g_vout[(e0 + 0) * Dc + b0 + 0] = pv0.x;
                    g_vout[(e0 + 1) * Dc + b0 + 0] = pv0.y;
                    g_vout[(e0 + 2) * Dc + b0 + 0] = pv0.z;
                    g_vout[(e0 + 3) * Dc + b0 + 0] = pv0.w;
                    g_vout[(e0 + 0) * Dc + b0 + 1] = pv1.x;
                    g_vout[(e0 + 1) * Dc + b0 + 1] = pv1.y;
                    g_vout[(e0 + 2) * Dc + b0 + 1] = pv1.z;
                    g_vout[(e0 + 3) * Dc + b0 + 1] = pv1.w;
                    g_vout[(e0 + 0) * Dc + b0 + 2] = pv2.x;
                    g_vout[(e0 + 1) * Dc + b0 + 2] = pv2.y;
                    g_vout[(e0 + 2) * Dc + b0 + 2] = pv2.z;
                    g_vout[(e0 + 3) * Dc + b0 + 2] = pv2.w;
                }
            }
        }
        __syncwarp();
    }
}

// ---------------- softmax exp + denom ----------------
__global__ void k_exp(const int* __restrict__ eidx) {
    int e = blockIdx.x * blockDim.x + threadIdx.x;
    if (e >= NEDGES) return;
    int src = eidx[NEDGES + e];
    float m = g_m[src];
    if (!isfinite(m)) m = 0.f;
    float ev = expf(g_attn[e] - m);
    g_expv[e] = ev;
    atomicAdd(&g_denom[src], ev);
}

// ---------------- scatter v*a ----------------
__global__ void k_scatter(const int* __restrict__ eidx) {
    int idx = blockIdx.x * blockDim.x + threadIdx.x;
    if (idx >= NEDGES * Dc) return;
    int e = idx / Dc;
    int c = idx - e * Dc;
    int src = eidx[NEDGES + e];
    float a = g_expv[e] / g_denom[src];
    atomicAdd(&g_upd[src * Dc + c], g_vout[idx] * a);
}

// ---------------- batchnorm stats ----------------
__global__ void k_bnstats(const float* __restrict__ atom) {
    __shared__ float r1[256], r2[256];
    int b = blockIdx.x;  // 0..15 scalar channels, 16..23 vector channels
    int tid = threadIdx.x;
    float s1 = 0.f, s2 = 0.f;
    if (b < 16) {
        for (int n = tid; n < NNODES; n += 256) {
            float y = atom[n * Dc + b] + g_upd[n * Dc + b];
            s1 += y;
            s2 += y * y;
        }
    } else {
        int i = b - 16;
        for (int n = tid; n < NNODES; n += 256) {
            int base = n * Dc + 16 + 3 * i;
            float y0 = atom[base + 0] + g_upd[base + 0];
            float y1 = atom[base + 1] + g_upd[base + 1];
            float y2 = atom[base + 2] + g_upd[base + 2];
            s1 += y0 * y0 + y1 * y1 + y2 * y2;
        }
    }
    r1[tid] = s1; r2[tid] = s2;
    __syncthreads();
    for (int off = 128; off > 0; off >>= 1) {
        if (tid < off) { r1[tid] += r1[tid + off]; r2[tid] += r2[tid + off]; }
        __syncthreads();
    }
    if (tid == 0) {
        if (b < 16) { g_bn[b] = r1[0]; g_bn[16 + b] = r2[0]; }
        else        { g_bn[16 + b] = r1[0]; }  // slots 32..39
    }
}

// ---------------- final output ----------------
__global__ void k_out(const float* __restrict__ atom,
                      const float* __restrict__ bws, const float* __restrict__ bbs,
                      const float* __restrict__ bwv, float* __restrict__ out) {
    int idx = blockIdx.x * blockDim.x + threadIdx.x;
    if (idx >= NNODES * Dc) return;
    int n = idx / Dc;
    int c = idx - n * Dc;
    float y = atom[idx] + g_upd[idx];
    float r;
    if (c < 16) {
        float mu = g_bn[c] * (1.f / NNODES);
        float var = g_bn[16 + c] * (1.f / NNODES) - mu * mu;
        r = (y - mu) * rsqrtf(var + EPSf) * bws[c] + bbs[c];
    } else {
        int i = (c - 16) / 3;
        float norm = g_bn[32 + i] * (1.f / (3.f * NNODES));
        r = y * rsqrtf(norm + EPSf) * bwv[i];
    }
    out[idx] = r;
}

// ---------------- launch ----------------
extern "C" void kernel_launch(void* const* d_in, const int* in_sizes, int n_in,
                              void* d_out, int out_size) {
    const float* atom = (const float*)d_in[0];
    const float* efeat = (const float*)d_in[1];
    const float* esh  = (const float*)d_in[2];
    const float* Wqs  = (const float*)d_in[3];
    const float* Wqv  = (const float*)d_in[4];
    const float* kw1  = (const float*)d_in[5];
    const float* kb1  = (const float*)d_in[6];
    const float* kw2  = (const float*)d_in[7];
    const float* kb2  = (const float*)d_in[8];
    const float* vw1  = (const float*)d_in[9];
    const float* vb1  = (const float*)d_in[10];
    const float* vw2  = (const float*)d_in[11];
    const float* vb2  = (const float*)d_in[12];
    const float* bws  = (const float*)d_in[13];
    const float* bbs  = (const float*)d_in[14];
    const float* bwv  = (const float*)d_in[15];
    const int*   eidx = (const int*)d_in[16];
    float* out = (float*)d_out;

    cudaFuncSetAttribute(k_edge, cudaFuncAttributeMaxDynamicSharedMemorySize,
                         SMEM_EDGE_BYTES);

    k_init<<<(NNODES * Dc + 255) / 256, 256>>>();
    k_q<<<(NNODES + 255) / 256, 256>>>(atom, Wqs, Wqv);
    k_edge<<<148, 256, SMEM_EDGE_BYTES>>>(atom, efeat, esh,
                                          kw1, kb1, kw2, kb2,
                                          vw1, vb1, vw2, vb2, eidx);
    k_exp<<<(NEDGES + 255) / 256, 256>>>(eidx);
    k_scatter<<<(NEDGES * Dc + 255) / 256, 256>>>(eidx);
    k_bnstats<<<24, 256>>>(atom);
    k_out<<<(NNODES * Dc + 255) / 256, 256>>>(atom, bws, bbs, bwv, out);

    long long need = (long long)NNODES * Dc + (long long)NEDGES * HEc;
    if (out_size >= need) {
        cudaMemcpyAsync(out + NNODES * Dc, efeat,
                        (size_t)NEDGES * HEc * sizeof(float),
                        cudaMemcpyDeviceToDevice);
    }
}